// round 13
// baseline (speedup 1.0000x reference)
#include <cuda_runtime.h>
#include <cstdint>

// Problem constants (fixed by the dataset)
#define BB      8
#define NG      4096
#define NO      4096

#define NBIN    256            // x micro-bins for the clustering sort
#define XLO     (-2.0f)
#define XIW     (64.0f)        // 256 bins / 4.0 span
#define XBW     (1.0f / XIW)   // bin width

#define OT_SIZE 128            // off-grid tile (pairs: 64)
#define N_OT    (NO / OT_SIZE) // 32
#define GT_SIZE 256            // grid tile per block (128 thr x GPT 2)
#define N_GT    (NG / GT_SIZE) // 16
#define ZS      8              // off-tile split across blocks (4 candidates each)

#define S_CUT   30.0f          // skip when min possible |s| exceeds this (w < 1e-9)
#define HL2E    0.72134752044448170f   // 0.5*log2(e)

// ---- device scratch (static; re-initialized inside kernels each launch) ----
__device__ float4 d_sxP[BB][NO/2];   // (sx_i, sx_j, sy_i, sy_j), sx=2K0*bx, sy=2K1*by
__device__ float2 d_cbP[BB][NO/2];   // (cb_i, cb_j), cb = -(K0 bx^2 + K1 by^2)
__device__ float4 d_yP [BB][NO/2];   // (y0_i, y0_j, y1_i, y1_j)
__device__ float4 d_gX [BB][NG];     // (x0, x1, cA, orig_idx bits), sorted by x0
__device__ float2 d_obnd[BB][N_OT];  // off tile (xlo, xhi)  -- bin-edge bounds
__device__ float2 d_gbnd[BB][N_GT];  // grid tile (xlo, xhi)
__device__ float2 g_partial[ZS][BB][NG];
__device__ unsigned g_tickets[BB][N_GT];   // monotonic; mod-ZS arrival test
__device__ int d_curs[BB][2][NBIN];
__device__ int d_offs[BB][2][NBIN];

// ---- packed f32x2 helpers (sm_100+, .b64 operands) ----
__device__ __forceinline__ uint64_t pk2(float lo, float hi) {
    uint64_t r; asm("mov.b64 %0, {%1,%2};" : "=l"(r) : "f"(lo), "f"(hi)); return r;
}
__device__ __forceinline__ void unpk2(uint64_t v, float& lo, float& hi) {
    asm("mov.b64 {%0,%1}, %2;" : "=f"(lo), "=f"(hi) : "l"(v));
}
__device__ __forceinline__ uint64_t add2(uint64_t a, uint64_t b) {
    uint64_t r; asm("add.rn.f32x2 %0, %1, %2;" : "=l"(r) : "l"(a), "l"(b)); return r;
}
__device__ __forceinline__ uint64_t fma2(uint64_t a, uint64_t b, uint64_t c) {
    uint64_t r; asm("fma.rn.f32x2 %0, %1, %2, %3;" : "=l"(r) : "l"(a), "l"(b), "l"(c)); return r;
}
__device__ __forceinline__ float ex2(float x) {
    float r; asm("ex2.approx.ftz.f32 %0, %1;" : "=f"(r) : "f"(x)); return r;
}

__device__ __forceinline__ int xbin(float x) {
    float fb = fminf((float)(NBIN - 1), fmaxf(0.f, floorf((x - XLO) * XIW)));
    return (int)fb;
}

// ============ K1: fused hist + scan + tile bounds (8 blocks) ============
__global__ void __launch_bounds__(256) prep_fused(
    const float* __restrict__ xo, const float* __restrict__ xg)
{
    __shared__ int h0[NBIN], h1[NBIN], c0[NBIN], c1[NBIN];
    const int b = blockIdx.x, tid = threadIdx.x;

    h0[tid] = 0; h1[tid] = 0;
    d_curs[b][0][tid] = 0;
    d_curs[b][1][tid] = 0;
    __syncthreads();

    // shared-memory histograms
    for (int i = tid; i < NO; i += 256)
        atomicAdd(&h0[xbin(xo[((size_t)b * NO + i) * 2])], 1);
    for (int i = tid; i < NG; i += 256)
        atomicAdd(&h1[xbin(xg[((size_t)b * NG + i) * 2])], 1);
    __syncthreads();

    // inclusive scans (256 threads == NBIN)
    c0[tid] = h0[tid]; c1[tid] = h1[tid];
    __syncthreads();
    for (int off = 1; off < NBIN; off <<= 1) {
        int v0 = (tid >= off) ? c0[tid - off] : 0;
        int v1 = (tid >= off) ? c1[tid - off] : 0;
        __syncthreads();
        c0[tid] += v0; c1[tid] += v1;
        __syncthreads();
    }
    d_offs[b][0][tid] = c0[tid] - h0[tid];   // exclusive
    d_offs[b][1][tid] = c1[tid] - h1[tid];
    __syncthreads();

    // tile x-bounds from bin edges (conservative by <= 1 bin width)
    if (tid < N_OT + N_GT) {
        const int* cum;
        int p0, p1;
        if (tid < N_OT) { cum = c0; p0 = tid * OT_SIZE; p1 = p0 + OT_SIZE - 1; }
        else { cum = c1; p0 = (tid - N_OT) * GT_SIZE; p1 = p0 + GT_SIZE - 1; }
        int blo = -1, bhi = -1;
        for (int k = 0; k < NBIN; k++) {
            int cv = cum[k];
            if (blo < 0 && cv > p0) blo = k;
            if (bhi < 0 && cv > p1) { bhi = k; break; }
        }
        if (bhi < 0) bhi = NBIN - 1;
        float xlo = (blo == 0)        ? -1e9f : XLO + blo * XBW;
        float xhi = (bhi == NBIN - 1) ?  1e9f : XLO + (bhi + 1) * XBW;
        if (tid < N_OT) d_obnd[b][tid] = make_float2(xlo, xhi);
        else            d_gbnd[b][tid - N_OT] = make_float2(xlo, xhi);
    }
}

// ============ K2: scatter (wide: 16 blocks/batch x 2 roles) ============
__global__ void __launch_bounds__(256) scatter_kernel(
    const float* __restrict__ xo, const float* __restrict__ yo,
    const float* __restrict__ xg, const float* __restrict__ lsp)
{
    const int b = blockIdx.y;
    const int i = blockIdx.x * 256 + threadIdx.x;    // 16*256 = 4096 points

    const float ls0 = 1e-5f + log1pf(expf(lsp[0]));
    const float ls1 = 1e-5f + log1pf(expf(lsp[1]));
    const float K0 = HL2E / (ls0 * ls0);
    const float K1v = HL2E / (ls1 * ls1);

    if (blockIdx.z == 0) {
        // off point
        float bx = xo[((size_t)b * NO + i) * 2];
        float by = xo[((size_t)b * NO + i) * 2 + 1];
        float y0 = yo[((size_t)b * NO + i) * 2];
        float y1 = yo[((size_t)b * NO + i) * 2 + 1];
        int bin = xbin(bx);
        int pos = d_offs[b][0][bin] + atomicAdd(&d_curs[b][0][bin], 1);
        int pr = pos >> 1, ln = pos & 1;
        float* sp = (float*)&d_sxP[b][pr];
        sp[ln]     = 2.f * K0 * bx;
        sp[2 + ln] = 2.f * K1v * by;
        ((float*)&d_cbP[b][pr])[ln] = -(K0 * bx * bx + K1v * by * by);
        float* yp = (float*)&d_yP[b][pr];
        yp[ln]     = y0;
        yp[2 + ln] = y1;
    } else {
        // grid point
        float x0 = xg[((size_t)b * NG + i) * 2];
        float x1 = xg[((size_t)b * NG + i) * 2 + 1];
        int bin = xbin(x0);
        int pos = d_offs[b][1][bin] + atomicAdd(&d_curs[b][1][bin], 1);
        d_gX[b][pos] = make_float4(x0, x1, -(K0 * x0 * x0 + K1v * x1 * x1),
                                   __int_as_float(i));
    }
}

// ================= K3: main conv with tile skipping ===================
__global__ void __launch_bounds__(128) conv_main(
    const float* __restrict__ yg,    // [B, NG, 2] (original order)
    const float* __restrict__ lsp,
    float* __restrict__ out)
{
    __shared__ float4 ssx[OT_SIZE / 2];
    __shared__ float2 scb[OT_SIZE / 2];
    __shared__ float4 syy[OT_SIZE / 2];
    __shared__ int    s_do_reduce;

    const int gt = blockIdx.x, b = blockIdx.y, z = blockIdx.z;
    const int tid = threadIdx.x;

    const float ls0 = 1e-5f + log1pf(expf(lsp[0]));
    const float K0 = HL2E / (ls0 * ls0);

    // this thread's two grid points (same tile -> same skip set)
    const int pos0 = gt * GT_SIZE + tid;
    const int pos1 = pos0 + 128;
    float4 gv0 = d_gX[b][pos0];
    float4 gv1 = d_gX[b][pos1];
    const uint64_t a00_0 = pk2(gv0.x, gv0.x);
    const uint64_t a11_0 = pk2(gv0.y, gv0.y);
    const uint64_t cA2_0 = pk2(gv0.z, gv0.z);
    const uint64_t a00_1 = pk2(gv1.x, gv1.x);
    const uint64_t a11_1 = pk2(gv1.y, gv1.y);
    const uint64_t cA2_1 = pk2(gv1.z, gv1.z);

    uint64_t p00 = 0ull, p01 = 0ull, p10 = 0ull, p11 = 0ull;

    uint32_t usx, ucb, uyy;
    asm("{ .reg .u64 t; cvta.to.shared.u64 t, %1; cvt.u32.u64 %0, t; }"
        : "=r"(usx) : "l"((const void*)ssx));
    asm("{ .reg .u64 t; cvta.to.shared.u64 t, %1; cvt.u32.u64 %0, t; }"
        : "=r"(ucb) : "l"((const void*)scb));
    asm("{ .reg .u64 t; cvta.to.shared.u64 t, %1; cvt.u32.u64 %0, t; }"
        : "=r"(uyy) : "l"((const void*)syy));

    const float2 gbd = d_gbnd[b][gt];

    for (int c = 0; c < N_OT / ZS; c++) {
        const int ot = z + c * ZS;
        float2 obd = d_obnd[b][ot];
        float gap = fmaxf(0.f, fmaxf(obd.x - gbd.y, gbd.x - obd.y));
        if (K0 * gap * gap > S_CUT) continue;   // block-uniform branch

        __syncthreads();   // prior tile fully consumed before overwrite
        if (tid < 64) {
            ssx[tid] = d_sxP[b][ot * 64 + tid];
            scb[tid] = d_cbP[b][ot * 64 + tid];
        } else {
            syy[tid - 64] = d_yP[b][ot * 64 + tid - 64];
        }
        __syncthreads();

#pragma unroll 8
        for (int m = 0; m < OT_SIZE / 2; m++) {
            uint64_t bx2, by2, cb2, y02, y12;
            asm("ld.shared.v2.b64 {%0,%1}, [%2];"
                : "=l"(bx2), "=l"(by2) : "r"(usx + m * 16));
            asm("ld.shared.b64 %0, [%1];"
                : "=l"(cb2) : "r"(ucb + m * 8));
            asm("ld.shared.v2.b64 {%0,%1}, [%2];"
                : "=l"(y02), "=l"(y12) : "r"(uyy + m * 16));

            // grid point 0
            uint64_t s0 = fma2(bx2, a00_0, cb2);
            s0 = fma2(by2, a11_0, s0);
            s0 = add2(s0, cA2_0);
            float si, sj;
            unpk2(s0, si, sj);
            uint64_t w0 = pk2(ex2(si), ex2(sj));
            p00 = fma2(w0, y02, p00);
            p01 = fma2(w0, y12, p01);

            // grid point 1
            uint64_t s1 = fma2(bx2, a00_1, cb2);
            s1 = fma2(by2, a11_1, s1);
            s1 = add2(s1, cA2_1);
            unpk2(s1, si, sj);
            uint64_t w1 = pk2(ex2(si), ex2(sj));
            p10 = fma2(w1, y02, p10);
            p11 = fma2(w1, y12, p11);
        }
    }

    {
        float e, o, e1, o1;
        unpk2(p00, e, o);  unpk2(p01, e1, o1);
        g_partial[z][b][pos0] = make_float2(e + o, e1 + o1);
        unpk2(p10, e, o);  unpk2(p11, e1, o1);
        g_partial[z][b][pos1] = make_float2(e + o, e1 + o1);
    }

    // ---- fused reduction: last-arriving z for this (b, gt) reduces ----
    __threadfence();
    if (tid == 0) {
        unsigned old = atomicAdd(&g_tickets[b][gt], 1u);
        s_do_reduce = ((old % ZS) == ZS - 1);
    }
    __syncthreads();
    if (!s_do_reduce) return;
    __threadfence();

    float4* outy = (float4*)(out + (size_t)BB * NG * 2);
#pragma unroll
    for (int k = 0; k < 2; k++) {
        int pos = (k == 0) ? pos0 : pos1;
        float4 gv = (k == 0) ? gv0 : gv1;
        int gorig = __float_as_int(gv.w);

        ((float2*)out)[(size_t)b * NG + gorig] = make_float2(gv.x, gv.y);
        float2 yon = ((const float2*)yg)[(size_t)b * NG + gorig];

        float sxr = 0.f, syr = 0.f;
#pragma unroll
        for (int p = 0; p < ZS; p++) {   // fixed order
            float2 v = g_partial[p][b][pos];
            sxr += v.x;
            syr += v.y;
        }
        outy[(size_t)b * NG + gorig] = make_float4(yon.x, yon.y, sxr, syr);
    }
}

extern "C" void kernel_launch(void* const* d_in, const int* in_sizes, int n_in,
                              void* d_out, int out_size) {
    const float* xo  = (const float*)d_in[0];  // xc_off_grid
    const float* yo  = (const float*)d_in[1];  // yc_off_grid
    const float* xg  = (const float*)d_in[2];  // xc_on_grid
    const float* yg  = (const float*)d_in[3];  // yc_on_grid
    const float* lsp = (const float*)d_in[4];  // lengthscale_param

    prep_fused<<<BB, 256>>>(xo, xg);
    scatter_kernel<<<dim3(16, BB, 2), 256>>>(xo, yo, xg, lsp);
    conv_main<<<dim3(N_GT, BB, ZS), 128>>>(yg, lsp, (float*)d_out);
}

// round 14
// speedup vs baseline: 1.1810x; 1.1810x over previous
#include <cuda_runtime.h>
#include <cstdint>

// Problem constants (fixed by the dataset)
#define BB      8
#define NG      4096
#define NO      4096

#define NBIN    256            // x micro-bins for the clustering sort
#define XLO     (-2.0f)
#define XIW     (64.0f)        // 256 bins / 4.0 span
#define XBW     (1.0f / XIW)   // bin width

#define OT_SIZE 128            // off-grid tile (pairs: 64)
#define N_OT    (NO / OT_SIZE) // 32
#define GT_SIZE 256            // grid tile per block (128 thr x GPT 2)
#define N_GT    (NG / GT_SIZE) // 16
#define ZS      8              // off-tile split across blocks (4 candidates each)

#define S_CUT   30.0f          // skip when min possible |s| exceeds this (w < 1e-9)
#define HL2E    0.72134752044448170f   // 0.5*log2(e)

// ---- device scratch (zero-init; each replay leaves it re-zeroed) ----
__device__ float4 d_sxP[BB][NO/2];   // (sx_i, sx_j, sy_i, sy_j), sx=2K0*bx, sy=2K1*by
__device__ float2 d_cbP[BB][NO/2];   // (cb_i, cb_j), cb = -(K0 bx^2 + K1 by^2)
__device__ float4 d_yP [BB][NO/2];   // (y0_i, y0_j, y1_i, y1_j)
__device__ float4 d_gX [BB][NG];     // (x0, x1, cA, orig_idx bits), sorted by x0
__device__ float2 d_obnd[BB][N_OT];  // off tile (xlo, xhi)  -- bin-edge bounds
__device__ float2 d_gbnd[BB][N_GT];  // grid tile (xlo, xhi)
__device__ float2 g_partial[ZS][BB][NG];
__device__ unsigned g_tickets[BB][N_GT];   // monotonic; mod-ZS arrival test
__device__ int d_hist[BB][2][NBIN];  // zeroed by scan_bounds each replay
__device__ int d_curs[BB][2][NBIN];  // zeroed by scan_bounds each replay
__device__ int d_offs[BB][2][NBIN];

// ---- packed f32x2 helpers (sm_100+, .b64 operands) ----
__device__ __forceinline__ uint64_t pk2(float lo, float hi) {
    uint64_t r; asm("mov.b64 %0, {%1,%2};" : "=l"(r) : "f"(lo), "f"(hi)); return r;
}
__device__ __forceinline__ void unpk2(uint64_t v, float& lo, float& hi) {
    asm("mov.b64 {%0,%1}, %2;" : "=f"(lo), "=f"(hi) : "l"(v));
}
__device__ __forceinline__ uint64_t add2(uint64_t a, uint64_t b) {
    uint64_t r; asm("add.rn.f32x2 %0, %1, %2;" : "=l"(r) : "l"(a), "l"(b)); return r;
}
__device__ __forceinline__ uint64_t fma2(uint64_t a, uint64_t b, uint64_t c) {
    uint64_t r; asm("fma.rn.f32x2 %0, %1, %2, %3;" : "=l"(r) : "l"(a), "l"(b), "l"(c)); return r;
}
__device__ __forceinline__ float ex2(float x) {
    float r; asm("ex2.approx.ftz.f32 %0, %1;" : "=f"(r) : "f"(x)); return r;
}

__device__ __forceinline__ int xbin(float x) {
    float fb = fminf((float)(NBIN - 1), fmaxf(0.f, floorf((x - XLO) * XIW)));
    return (int)fb;
}

// ============ K1: histograms (wide: 16 blocks/batch) ============
__global__ void __launch_bounds__(256) hist_kernel(
    const float* __restrict__ xo, const float* __restrict__ xg)
{
    const int b = blockIdx.y;
    const int i = blockIdx.x * 256 + threadIdx.x;    // 16*256 = 4096
    atomicAdd(&d_hist[b][0][xbin(xo[((size_t)b * NO + i) * 2])], 1);
    atomicAdd(&d_hist[b][1][xbin(xg[((size_t)b * NG + i) * 2])], 1);
}

// ============ K2: scan + bounds + state reset (8 blocks) ============
__global__ void __launch_bounds__(256) scan_bounds_kernel() {
    __shared__ int c0[NBIN], c1[NBIN];
    const int b = blockIdx.x, tid = threadIdx.x;

    const int h0 = d_hist[b][0][tid];
    const int h1 = d_hist[b][1][tid];
    d_hist[b][0][tid] = 0;            // reset for next graph replay
    d_hist[b][1][tid] = 0;
    d_curs[b][0][tid] = 0;
    d_curs[b][1][tid] = 0;

    c0[tid] = h0; c1[tid] = h1;
    __syncthreads();
    for (int off = 1; off < NBIN; off <<= 1) {
        int v0 = (tid >= off) ? c0[tid - off] : 0;
        int v1 = (tid >= off) ? c1[tid - off] : 0;
        __syncthreads();
        c0[tid] += v0; c1[tid] += v1;   // inclusive
        __syncthreads();
    }
    d_offs[b][0][tid] = c0[tid] - h0;   // exclusive
    d_offs[b][1][tid] = c1[tid] - h1;

    // Parallel tile bounds: thread k owns bin k = cum range [prev, cum).
    // Tile t's first/last sorted positions p0/p1 land in exactly one bin each.
    const int prev0 = (tid == 0) ? 0 : c0[tid - 1];
    const int prev1 = (tid == 0) ? 0 : c1[tid - 1];
    const float elo = (tid == 0)        ? -1e9f : XLO + tid * XBW;
    const float ehi = (tid == NBIN - 1) ?  1e9f : XLO + (tid + 1) * XBW;
#pragma unroll
    for (int t = 0; t < N_OT; t++) {
        int p0 = t * OT_SIZE, p1 = p0 + OT_SIZE - 1;
        if (prev0 <= p0 && p0 < c0[tid]) d_obnd[b][t].x = elo;
        if (prev0 <= p1 && p1 < c0[tid]) d_obnd[b][t].y = ehi;
    }
#pragma unroll
    for (int t = 0; t < N_GT; t++) {
        int p0 = t * GT_SIZE, p1 = p0 + GT_SIZE - 1;
        if (prev1 <= p0 && p0 < c1[tid]) d_gbnd[b][t].x = elo;
        if (prev1 <= p1 && p1 < c1[tid]) d_gbnd[b][t].y = ehi;
    }
}

// ============ K3: scatter (wide: 16 blocks/batch x 2 roles) ============
__global__ void __launch_bounds__(256) scatter_kernel(
    const float* __restrict__ xo, const float* __restrict__ yo,
    const float* __restrict__ xg, const float* __restrict__ lsp)
{
    const int b = blockIdx.y;
    const int i = blockIdx.x * 256 + threadIdx.x;    // 16*256 = 4096 points

    const float ls0 = 1e-5f + log1pf(expf(lsp[0]));
    const float ls1 = 1e-5f + log1pf(expf(lsp[1]));
    const float K0 = HL2E / (ls0 * ls0);
    const float K1v = HL2E / (ls1 * ls1);

    if (blockIdx.z == 0) {
        // off point
        float bx = xo[((size_t)b * NO + i) * 2];
        float by = xo[((size_t)b * NO + i) * 2 + 1];
        float y0 = yo[((size_t)b * NO + i) * 2];
        float y1 = yo[((size_t)b * NO + i) * 2 + 1];
        int bin = xbin(bx);
        int pos = d_offs[b][0][bin] + atomicAdd(&d_curs[b][0][bin], 1);
        int pr = pos >> 1, ln = pos & 1;
        float* sp = (float*)&d_sxP[b][pr];
        sp[ln]     = 2.f * K0 * bx;
        sp[2 + ln] = 2.f * K1v * by;
        ((float*)&d_cbP[b][pr])[ln] = -(K0 * bx * bx + K1v * by * by);
        float* yp = (float*)&d_yP[b][pr];
        yp[ln]     = y0;
        yp[2 + ln] = y1;
    } else {
        // grid point
        float x0 = xg[((size_t)b * NG + i) * 2];
        float x1 = xg[((size_t)b * NG + i) * 2 + 1];
        int bin = xbin(x0);
        int pos = d_offs[b][1][bin] + atomicAdd(&d_curs[b][1][bin], 1);
        d_gX[b][pos] = make_float4(x0, x1, -(K0 * x0 * x0 + K1v * x1 * x1),
                                   __int_as_float(i));
    }
}

// ================= K4: main conv with tile skipping ===================
__global__ void __launch_bounds__(128) conv_main(
    const float* __restrict__ yg,    // [B, NG, 2] (original order)
    const float* __restrict__ lsp,
    float* __restrict__ out)
{
    __shared__ float4 ssx[OT_SIZE / 2];
    __shared__ float2 scb[OT_SIZE / 2];
    __shared__ float4 syy[OT_SIZE / 2];
    __shared__ int    s_do_reduce;

    const int gt = blockIdx.x, b = blockIdx.y, z = blockIdx.z;
    const int tid = threadIdx.x;

    const float ls0 = 1e-5f + log1pf(expf(lsp[0]));
    const float K0 = HL2E / (ls0 * ls0);

    // this thread's two grid points (same tile -> same skip set)
    const int pos0 = gt * GT_SIZE + tid;
    const int pos1 = pos0 + 128;
    float4 gv0 = d_gX[b][pos0];
    float4 gv1 = d_gX[b][pos1];
    const uint64_t a00_0 = pk2(gv0.x, gv0.x);
    const uint64_t a11_0 = pk2(gv0.y, gv0.y);
    const uint64_t cA2_0 = pk2(gv0.z, gv0.z);
    const uint64_t a00_1 = pk2(gv1.x, gv1.x);
    const uint64_t a11_1 = pk2(gv1.y, gv1.y);
    const uint64_t cA2_1 = pk2(gv1.z, gv1.z);

    uint64_t p00 = 0ull, p01 = 0ull, p10 = 0ull, p11 = 0ull;

    uint32_t usx, ucb, uyy;
    asm("{ .reg .u64 t; cvta.to.shared.u64 t, %1; cvt.u32.u64 %0, t; }"
        : "=r"(usx) : "l"((const void*)ssx));
    asm("{ .reg .u64 t; cvta.to.shared.u64 t, %1; cvt.u32.u64 %0, t; }"
        : "=r"(ucb) : "l"((const void*)scb));
    asm("{ .reg .u64 t; cvta.to.shared.u64 t, %1; cvt.u32.u64 %0, t; }"
        : "=r"(uyy) : "l"((const void*)syy));

    const float2 gbd = d_gbnd[b][gt];

    for (int c = 0; c < N_OT / ZS; c++) {
        const int ot = z + c * ZS;
        float2 obd = d_obnd[b][ot];
        float gap = fmaxf(0.f, fmaxf(obd.x - gbd.y, gbd.x - obd.y));
        if (K0 * gap * gap > S_CUT) continue;   // block-uniform branch

        __syncthreads();   // prior tile fully consumed before overwrite
        if (tid < 64) {
            ssx[tid] = d_sxP[b][ot * 64 + tid];
            scb[tid] = d_cbP[b][ot * 64 + tid];
        } else {
            syy[tid - 64] = d_yP[b][ot * 64 + tid - 64];
        }
        __syncthreads();

#pragma unroll 8
        for (int m = 0; m < OT_SIZE / 2; m++) {
            uint64_t bx2, by2, cb2, y02, y12;
            asm("ld.shared.v2.b64 {%0,%1}, [%2];"
                : "=l"(bx2), "=l"(by2) : "r"(usx + m * 16));
            asm("ld.shared.b64 %0, [%1];"
                : "=l"(cb2) : "r"(ucb + m * 8));
            asm("ld.shared.v2.b64 {%0,%1}, [%2];"
                : "=l"(y02), "=l"(y12) : "r"(uyy + m * 16));

            // grid point 0
            uint64_t s0 = fma2(bx2, a00_0, cb2);
            s0 = fma2(by2, a11_0, s0);
            s0 = add2(s0, cA2_0);
            float si, sj;
            unpk2(s0, si, sj);
            uint64_t w0 = pk2(ex2(si), ex2(sj));
            p00 = fma2(w0, y02, p00);
            p01 = fma2(w0, y12, p01);

            // grid point 1
            uint64_t s1 = fma2(bx2, a00_1, cb2);
            s1 = fma2(by2, a11_1, s1);
            s1 = add2(s1, cA2_1);
            unpk2(s1, si, sj);
            uint64_t w1 = pk2(ex2(si), ex2(sj));
            p10 = fma2(w1, y02, p10);
            p11 = fma2(w1, y12, p11);
        }
    }

    {
        float e, o, e1, o1;
        unpk2(p00, e, o);  unpk2(p01, e1, o1);
        g_partial[z][b][pos0] = make_float2(e + o, e1 + o1);
        unpk2(p10, e, o);  unpk2(p11, e1, o1);
        g_partial[z][b][pos1] = make_float2(e + o, e1 + o1);
    }

    // ---- fused reduction: last-arriving z for this (b, gt) reduces ----
    __threadfence();
    if (tid == 0) {
        unsigned old = atomicAdd(&g_tickets[b][gt], 1u);
        s_do_reduce = ((old % ZS) == ZS - 1);
    }
    __syncthreads();
    if (!s_do_reduce) return;
    __threadfence();

    float4* outy = (float4*)(out + (size_t)BB * NG * 2);
#pragma unroll
    for (int k = 0; k < 2; k++) {
        int pos = (k == 0) ? pos0 : pos1;
        float4 gv = (k == 0) ? gv0 : gv1;
        int gorig = __float_as_int(gv.w);

        ((float2*)out)[(size_t)b * NG + gorig] = make_float2(gv.x, gv.y);
        float2 yon = ((const float2*)yg)[(size_t)b * NG + gorig];

        float sxr = 0.f, syr = 0.f;
#pragma unroll
        for (int p = 0; p < ZS; p++) {   // fixed order
            float2 v = g_partial[p][b][pos];
            sxr += v.x;
            syr += v.y;
        }
        outy[(size_t)b * NG + gorig] = make_float4(yon.x, yon.y, sxr, syr);
    }
}

extern "C" void kernel_launch(void* const* d_in, const int* in_sizes, int n_in,
                              void* d_out, int out_size) {
    const float* xo  = (const float*)d_in[0];  // xc_off_grid
    const float* yo  = (const float*)d_in[1];  // yc_off_grid
    const float* xg  = (const float*)d_in[2];  // xc_on_grid
    const float* yg  = (const float*)d_in[3];  // yc_on_grid
    const float* lsp = (const float*)d_in[4];  // lengthscale_param

    hist_kernel<<<dim3(16, BB), 256>>>(xo, xg);
    scan_bounds_kernel<<<BB, 256>>>();
    scatter_kernel<<<dim3(16, BB, 2), 256>>>(xo, yo, xg, lsp);
    conv_main<<<dim3(N_GT, BB, ZS), 128>>>(yg, lsp, (float*)d_out);
}